// round 1
// baseline (speedup 1.0000x reference)
#include <cuda_runtime.h>
#include <cstddef>

// Shapes (fixed for this problem): B=32, T=1024, D=H=1024, O=10.
// h2 = x @ W_comb^T + b_comb, where W_comb = W_hid @ W_proj,
// b_comb = W_hid @ b_proj + b_hid. Then LIF scan over T, mean-pool, head.

__device__ float g_wcomb[1024 * 1024];
__device__ float g_bcomb[1024];
__device__ float g_h2[32u * 1024u * 1024u];   // [B*T, H] = 134 MB scratch
__device__ float g_pooled[32 * 1024];

// ---------------------------------------------------------------------------
// Block reduction helper (256 threads)
// ---------------------------------------------------------------------------
__device__ __forceinline__ float block_reduce_sum(float v) {
    __shared__ float sh[8];
    int lane = threadIdx.x & 31;
    int w = threadIdx.x >> 5;
    #pragma unroll
    for (int o = 16; o > 0; o >>= 1) v += __shfl_down_sync(0xFFFFFFFFu, v, o);
    if (lane == 0) sh[w] = v;
    __syncthreads();
    if (w == 0) {
        v = (lane < 8) ? sh[lane] : 0.0f;
        #pragma unroll
        for (int o = 4; o > 0; o >>= 1) v += __shfl_down_sync(0xFFFFFFFFu, v, o);
    }
    return v;  // valid in thread 0
}

// ---------------------------------------------------------------------------
// SGEMM.  TRANS_B=true : C[m,n] = sum_k A[m,k] * B[n,k]   (B is [N,K])
//         TRANS_B=false: C[m,n] = sum_k A[m,k] * B[k,n]   (B is [K,N])
// Optional bias added along n. M % 128 == 0, N % 128 == 0, K % 16 == 0.
// ---------------------------------------------------------------------------
template <bool TRANS_B>
__global__ __launch_bounds__(256)
void sgemm_kernel(const float* __restrict__ A, const float* __restrict__ B,
                  const float* __restrict__ bias, float* __restrict__ C,
                  int M, int N, int K)
{
    constexpr int BM = 128, BN = 128, BK = 16, TM = 8, TN = 8;
    __shared__ float As[BK][BM];
    __shared__ float Bs[BK][BN];

    const int tid = threadIdx.x;
    const int m0 = blockIdx.y * BM;
    const int n0 = blockIdx.x * BN;
    const int tm = (tid >> 4) * TM;   // 16x16 thread grid over the 128x128 tile
    const int tn = (tid & 15) * TN;

    float acc[TM][TN];
    #pragma unroll
    for (int i = 0; i < TM; i++)
        #pragma unroll
        for (int j = 0; j < TN; j++) acc[i][j] = 0.0f;

    for (int k0 = 0; k0 < K; k0 += BK) {
        // ---- load A tile (128 rows x 16 cols), store transposed As[k][m]
        #pragma unroll
        for (int v = 0; v < 2; v++) {
            int idx = tid + v * 256;        // 0..511 float4 slots
            int r = idx >> 2;               // row 0..127
            int c4 = (idx & 3) * 4;         // col 0,4,8,12
            float4 t = *reinterpret_cast<const float4*>(
                A + (size_t)(m0 + r) * K + k0 + c4);
            As[c4 + 0][r] = t.x; As[c4 + 1][r] = t.y;
            As[c4 + 2][r] = t.z; As[c4 + 3][r] = t.w;
        }
        // ---- load B tile
        if (TRANS_B) {
            #pragma unroll
            for (int v = 0; v < 2; v++) {
                int idx = tid + v * 256;
                int r = idx >> 2;           // n-row 0..127
                int c4 = (idx & 3) * 4;
                float4 t = *reinterpret_cast<const float4*>(
                    B + (size_t)(n0 + r) * K + k0 + c4);
                Bs[c4 + 0][r] = t.x; Bs[c4 + 1][r] = t.y;
                Bs[c4 + 2][r] = t.z; Bs[c4 + 3][r] = t.w;
            }
        } else {
            #pragma unroll
            for (int v = 0; v < 2; v++) {
                int idx = tid + v * 256;
                int r = idx >> 5;           // k-row 0..15
                int c = (idx & 31) * 4;     // n col 0..124
                *reinterpret_cast<float4*>(&Bs[r][c]) =
                    *reinterpret_cast<const float4*>(
                        B + (size_t)(k0 + r) * N + n0 + c);
            }
        }
        __syncthreads();

        #pragma unroll
        for (int kk = 0; kk < BK; kk++) {
            float a[TM], b[TN];
            *reinterpret_cast<float4*>(&a[0]) =
                *reinterpret_cast<const float4*>(&As[kk][tm]);
            *reinterpret_cast<float4*>(&a[4]) =
                *reinterpret_cast<const float4*>(&As[kk][tm + 4]);
            *reinterpret_cast<float4*>(&b[0]) =
                *reinterpret_cast<const float4*>(&Bs[kk][tn]);
            *reinterpret_cast<float4*>(&b[4]) =
                *reinterpret_cast<const float4*>(&Bs[kk][tn + 4]);
            #pragma unroll
            for (int i = 0; i < TM; i++)
                #pragma unroll
                for (int j = 0; j < TN; j++)
                    acc[i][j] = fmaf(a[i], b[j], acc[i][j]);
        }
        __syncthreads();
    }

    // ---- epilogue
    #pragma unroll
    for (int i = 0; i < TM; i++) {
        int m = m0 + tm + i;
        #pragma unroll
        for (int j = 0; j < TN; j += 4) {
            int n = n0 + tn + j;
            float4 r;
            r.x = acc[i][j + 0]; r.y = acc[i][j + 1];
            r.z = acc[i][j + 2]; r.w = acc[i][j + 3];
            if (bias != nullptr) {
                r.x += bias[n + 0]; r.y += bias[n + 1];
                r.z += bias[n + 2]; r.w += bias[n + 3];
            }
            *reinterpret_cast<float4*>(C + (size_t)m * N + n) = r;
        }
    }
}

// ---------------------------------------------------------------------------
// b_comb[g] = sum_h W_hid[g,h] * b_proj[h] + b_hid[g]
// ---------------------------------------------------------------------------
__global__ __launch_bounds__(256)
void bias_comb_kernel(const float* __restrict__ W_hid,
                      const float* __restrict__ b_proj,
                      const float* __restrict__ b_hid,
                      float* __restrict__ bcomb)
{
    int g = blockIdx.x;
    float s = 0.0f;
    for (int h = threadIdx.x; h < 1024; h += 256)
        s = fmaf(W_hid[g * 1024 + h], b_proj[h], s);
    s = block_reduce_sum(s);
    if (threadIdx.x == 0) bcomb[g] = s + b_hid[g];
}

// ---------------------------------------------------------------------------
// LIF scan over T with soft reset + time-mean pooling of spikes.
// One thread per (b, g) sequence. Forward spike = hard threshold.
// ---------------------------------------------------------------------------
__global__ __launch_bounds__(256)
void lif_kernel(const float* __restrict__ h2, float* __restrict__ pooled)
{
    int idx = blockIdx.x * 256 + threadIdx.x;   // 0..32767
    int b = idx >> 10;
    int g = idx & 1023;
    const float* p = h2 + (size_t)b * 1024 * 1024 + g;

    float v = 0.0f;
    float acc = 0.0f;
    #pragma unroll 4
    for (int t = 0; t < 1024; t++) {
        float xv = __ldg(p + (size_t)t * 1024);
        // v = v + (x - v)/2, no FMA contraction (match ref op order)
        float dv = __fmul_rn(__fsub_rn(xv, v), 0.5f);
        v = __fadd_rn(v, dv);
        if (v >= 1.0f) { acc += 1.0f; v = __fsub_rn(v, 1.0f); }
    }
    pooled[idx] = acc * (1.0f / 1024.0f);
}

// ---------------------------------------------------------------------------
// out[b,o] = sum_g pooled[b,g] * W_out[o,g] + b_out[o]
// ---------------------------------------------------------------------------
__global__ __launch_bounds__(256)
void head_kernel(const float* __restrict__ pooled,
                 const float* __restrict__ W_out,
                 const float* __restrict__ b_out,
                 float* __restrict__ out)
{
    int b = blockIdx.x / 10;
    int o = blockIdx.x % 10;
    float s = 0.0f;
    for (int g = threadIdx.x; g < 1024; g += 256)
        s = fmaf(pooled[b * 1024 + g], W_out[o * 1024 + g], s);
    s = block_reduce_sum(s);
    if (threadIdx.x == 0) out[blockIdx.x] = s + b_out[o];
}

// ---------------------------------------------------------------------------
extern "C" void kernel_launch(void* const* d_in, const int* in_sizes, int n_in,
                              void* d_out, int out_size)
{
    (void)in_sizes; (void)n_in; (void)out_size;
    const float* x      = (const float*)d_in[0];   // [32,1024,1024]
    const float* W_proj = (const float*)d_in[1];   // [1024,1024]
    const float* b_proj = (const float*)d_in[2];   // [1024]
    const float* W_hid  = (const float*)d_in[3];   // [1024,1024]
    const float* b_hid  = (const float*)d_in[4];   // [1024]
    const float* W_out  = (const float*)d_in[5];   // [10,1024]
    const float* b_out  = (const float*)d_in[6];   // [10]
    float* out = (float*)d_out;                    // [32,10]

    float *wcomb, *bcomb, *h2, *pooled;
    cudaGetSymbolAddress((void**)&wcomb,  g_wcomb);
    cudaGetSymbolAddress((void**)&bcomb,  g_bcomb);
    cudaGetSymbolAddress((void**)&h2,     g_h2);
    cudaGetSymbolAddress((void**)&pooled, g_pooled);

    // 1) b_comb = W_hid @ b_proj + b_hid
    bias_comb_kernel<<<1024, 256>>>(W_hid, b_proj, b_hid, bcomb);

    // 2) W_comb[g,d] = sum_h W_hid[g,h] * W_proj[h,d]   (A @ B, B is [K,N])
    sgemm_kernel<false><<<dim3(8, 8), 256>>>(
        W_hid, W_proj, nullptr, wcomb, 1024, 1024, 1024);

    // 3) h2[n,g] = sum_d x[n,d] * W_comb[g,d] + b_comb[g]   (A @ B^T)
    sgemm_kernel<true><<<dim3(8, 256), 256>>>(
        x, wcomb, bcomb, h2, 32768, 1024, 1024);

    // 4) LIF scan + mean-pool over T
    lif_kernel<<<128, 256>>>(h2, pooled);

    // 5) classification head
    head_kernel<<<320, 256>>>(pooled, W_out, b_out, out);
}

// round 3
// speedup vs baseline: 2.4221x; 2.4221x over previous
#include <cuda_runtime.h>
#include <cuda_bf16.h>
#include <cstdint>
#include <cstddef>

#define DINL __device__ __forceinline__

// ---------------------------------------------------------------------------
// Scratch (device globals; no allocation allowed)
// ---------------------------------------------------------------------------
__device__ float g_wcomb[1024u * 1024u];
__device__ float g_bcomb[1024];
__device__ float g_h2[32u * 1024u * 1024u];     // [B*T, H] fp32 (134 MB)
__device__ float g_pooled[32 * 1024];
__device__ __align__(16) __nv_bfloat16 g_xhi[32u * 1024u * 1024u];
__device__ __align__(16) __nv_bfloat16 g_xlo[32u * 1024u * 1024u];
__device__ __align__(16) __nv_bfloat16 g_whi[1024u * 1024u];
__device__ __align__(16) __nv_bfloat16 g_wlo[1024u * 1024u];

// ---------------------------------------------------------------------------
// PTX helpers (baseline compute_103-safe: cp.async, ldmatrix, mma.sync)
// ---------------------------------------------------------------------------
DINL uint32_t smem_u32(const void* p) {
    uint32_t r;
    asm("{ .reg .u64 t; cvta.to.shared.u64 t, %1; cvt.u32.u64 %0, t; }"
        : "=r"(r) : "l"(p));
    return r;
}
DINL void cp16(uint32_t dst, const void* src) {
    asm volatile("cp.async.cg.shared.global [%0], [%1], 16;"
                 :: "r"(dst), "l"(src) : "memory");
}
DINL void cp_commit() { asm volatile("cp.async.commit_group;" ::: "memory"); }
template <int N> DINL void cp_wait() {
    asm volatile("cp.async.wait_group %0;" :: "n"(N) : "memory");
}
DINL void ldsm_x4(uint32_t* r, uint32_t addr) {
    asm volatile("ldmatrix.sync.aligned.m8n8.x4.shared.b16 {%0,%1,%2,%3}, [%4];"
                 : "=r"(r[0]), "=r"(r[1]), "=r"(r[2]), "=r"(r[3]) : "r"(addr));
}
DINL void mma_bf16(float* d, const uint32_t* a, const uint32_t* b) {
    asm volatile(
        "mma.sync.aligned.m16n8k16.row.col.f32.bf16.bf16.f32 "
        "{%0,%1,%2,%3}, {%4,%5,%6,%7}, {%8,%9}, {%0,%1,%2,%3};"
        : "+f"(d[0]), "+f"(d[1]), "+f"(d[2]), "+f"(d[3])
        : "r"(a[0]), "r"(a[1]), "r"(a[2]), "r"(a[3]), "r"(b[0]), "r"(b[1]));
}

// ---------------------------------------------------------------------------
// Block reduction helper (256 threads)
// ---------------------------------------------------------------------------
DINL float block_reduce_sum(float v) {
    __shared__ float sh[8];
    int lane = threadIdx.x & 31;
    int w = threadIdx.x >> 5;
    #pragma unroll
    for (int o = 16; o > 0; o >>= 1) v += __shfl_down_sync(0xFFFFFFFFu, v, o);
    if (lane == 0) sh[w] = v;
    __syncthreads();
    if (w == 0) {
        v = (lane < 8) ? sh[lane] : 0.0f;
        #pragma unroll
        for (int o = 4; o > 0; o >>= 1) v += __shfl_down_sync(0xFFFFFFFFu, v, o);
    }
    return v;
}

// ---------------------------------------------------------------------------
// fp32 SGEMM for W_comb = W_hid @ W_proj (1024^3, small)
// ---------------------------------------------------------------------------
__global__ __launch_bounds__(256)
void sgemm_nn_kernel(const float* __restrict__ A, const float* __restrict__ B,
                     float* __restrict__ C, int M, int N, int K)
{
    constexpr int BM = 128, BN = 128, BK = 16, TM = 8, TN = 8;
    __shared__ float As[BK][BM];
    __shared__ float Bs[BK][BN];

    const int tid = threadIdx.x;
    const int m0 = blockIdx.y * BM;
    const int n0 = blockIdx.x * BN;
    const int tm = (tid >> 4) * TM;
    const int tn = (tid & 15) * TN;

    float acc[TM][TN];
    #pragma unroll
    for (int i = 0; i < TM; i++)
        #pragma unroll
        for (int j = 0; j < TN; j++) acc[i][j] = 0.0f;

    for (int k0 = 0; k0 < K; k0 += BK) {
        #pragma unroll
        for (int v = 0; v < 2; v++) {
            int idx = tid + v * 256;
            int r = idx >> 2;
            int c4 = (idx & 3) * 4;
            float4 t = *reinterpret_cast<const float4*>(
                A + (size_t)(m0 + r) * K + k0 + c4);
            As[c4 + 0][r] = t.x; As[c4 + 1][r] = t.y;
            As[c4 + 2][r] = t.z; As[c4 + 3][r] = t.w;
        }
        #pragma unroll
        for (int v = 0; v < 2; v++) {
            int idx = tid + v * 256;
            int r = idx >> 5;
            int c = (idx & 31) * 4;
            *reinterpret_cast<float4*>(&Bs[r][c]) =
                *reinterpret_cast<const float4*>(B + (size_t)(k0 + r) * N + n0 + c);
        }
        __syncthreads();

        #pragma unroll
        for (int kk = 0; kk < BK; kk++) {
            float a[TM], b[TN];
            *reinterpret_cast<float4*>(&a[0]) = *reinterpret_cast<const float4*>(&As[kk][tm]);
            *reinterpret_cast<float4*>(&a[4]) = *reinterpret_cast<const float4*>(&As[kk][tm + 4]);
            *reinterpret_cast<float4*>(&b[0]) = *reinterpret_cast<const float4*>(&Bs[kk][tn]);
            *reinterpret_cast<float4*>(&b[4]) = *reinterpret_cast<const float4*>(&Bs[kk][tn + 4]);
            #pragma unroll
            for (int i = 0; i < TM; i++)
                #pragma unroll
                for (int j = 0; j < TN; j++)
                    acc[i][j] = fmaf(a[i], b[j], acc[i][j]);
        }
        __syncthreads();
    }

    #pragma unroll
    for (int i = 0; i < TM; i++) {
        int m = m0 + tm + i;
        #pragma unroll
        for (int j = 0; j < TN; j += 4) {
            int n = n0 + tn + j;
            float4 r;
            r.x = acc[i][j + 0]; r.y = acc[i][j + 1];
            r.z = acc[i][j + 2]; r.w = acc[i][j + 3];
            *reinterpret_cast<float4*>(C + (size_t)m * N + n) = r;
        }
    }
}

// ---------------------------------------------------------------------------
// b_comb[g] = sum_h W_hid[g,h] * b_proj[h] + b_hid[g]
// ---------------------------------------------------------------------------
__global__ __launch_bounds__(256)
void bias_comb_kernel(const float* __restrict__ W_hid,
                      const float* __restrict__ b_proj,
                      const float* __restrict__ b_hid,
                      float* __restrict__ bcomb)
{
    int g = blockIdx.x;
    float s = 0.0f;
    for (int h = threadIdx.x; h < 1024; h += 256)
        s = fmaf(W_hid[g * 1024 + h], b_proj[h], s);
    s = block_reduce_sum(s);
    if (threadIdx.x == 0) bcomb[g] = s + b_hid[g];
}

// ---------------------------------------------------------------------------
// fp32 -> (bf16 hi, bf16 lo) split, vectorized
// ---------------------------------------------------------------------------
__global__ __launch_bounds__(256)
void split_kernel(const float* __restrict__ src,
                  __nv_bfloat16* __restrict__ hi,
                  __nv_bfloat16* __restrict__ lo, int n4)
{
    int i = blockIdx.x * 256 + threadIdx.x;
    if (i >= n4) return;
    float4 v = reinterpret_cast<const float4*>(src)[i];
    float f[4] = {v.x, v.y, v.z, v.w};
    uint32_t hw[2], lw[2];
    #pragma unroll
    for (int j = 0; j < 2; j++) {
        __nv_bfloat16 h0 = __float2bfloat16(f[2 * j + 0]);
        __nv_bfloat16 h1 = __float2bfloat16(f[2 * j + 1]);
        __nv_bfloat16 l0 = __float2bfloat16(f[2 * j + 0] - __bfloat162float(h0));
        __nv_bfloat16 l1 = __float2bfloat16(f[2 * j + 1] - __bfloat162float(h1));
        unsigned short uh0 = *reinterpret_cast<unsigned short*>(&h0);
        unsigned short uh1 = *reinterpret_cast<unsigned short*>(&h1);
        unsigned short ul0 = *reinterpret_cast<unsigned short*>(&l0);
        unsigned short ul1 = *reinterpret_cast<unsigned short*>(&l1);
        hw[j] = (uint32_t)uh0 | ((uint32_t)uh1 << 16);
        lw[j] = (uint32_t)ul0 | ((uint32_t)ul1 << 16);
    }
    reinterpret_cast<uint2*>(hi)[i] = make_uint2(hw[0], hw[1]);
    reinterpret_cast<uint2*>(lo)[i] = make_uint2(lw[0], lw[1]);
}

// ---------------------------------------------------------------------------
// Main GEMM: h2[m,n] = sum_d x[m,d]*Wc[n,d] + bias[n], bf16x3 split via
// mma.sync.m16n8k16. Tile 128x128, BK=64, 8 warps (2x4), 3-stage cp.async.
// ---------------------------------------------------------------------------
static constexpr uint32_t STAGE = 65536u;   // Ahi16K Alo16K Bhi16K Blo16K
static constexpr int NCH = 16;              // K=1024 / 64

__global__ __launch_bounds__(256, 1)
void snn_gemm(const __nv_bfloat16* __restrict__ xhi,
              const __nv_bfloat16* __restrict__ xlo,
              const __nv_bfloat16* __restrict__ whi,
              const __nv_bfloat16* __restrict__ wlo,
              const float* __restrict__ bias,
              float* __restrict__ out)
{
    extern __shared__ __align__(1024) char smem[];
    const uint32_t sbase = smem_u32(smem);
    const int tid = threadIdx.x;
    const int wid = tid >> 5;
    const int lane = tid & 31;
    const int wm = (wid >> 2) * 64;      // warp m offset (2 rows of warps)
    const int wn = (wid & 3) * 32;       // warp n offset (4 cols of warps)
    const int m0 = blockIdx.y << 7;
    const int n0 = blockIdx.x << 7;

    float acc[4][4][4];                  // [m-tile 16][n-tile 8][frag]
    #pragma unroll
    for (int i = 0; i < 4; i++)
        #pragma unroll
        for (int j = 0; j < 4; j++)
            #pragma unroll
            for (int r = 0; r < 4; r++) acc[i][j][r] = 0.0f;

    auto load_stage = [&](int c, int s) {
        const uint32_t st = sbase + (uint32_t)s * STAGE;
        const int k0 = c << 6;
        #pragma unroll
        for (int it = 0; it < 4; it++) {
            int idx = it * 256 + tid;            // 0..1023
            int row = idx >> 3;
            int ch = idx & 7;
            uint32_t off = (uint32_t)(row * 128) +
                           (uint32_t)(((ch ^ (row & 7)) << 4));
            size_t ga = (size_t)(m0 + row) * 1024 + k0 + ch * 8;
            size_t gb = (size_t)(n0 + row) * 1024 + k0 + ch * 8;
            cp16(st + off,          xhi + ga);
            cp16(st + 16384u + off, xlo + ga);
            cp16(st + 32768u + off, whi + gb);
            cp16(st + 49152u + off, wlo + gb);
        }
        cp_commit();
    };

    auto compute_stage = [&](int s) {
        const uint32_t st = sbase + (uint32_t)s * STAGE;
        #pragma unroll
        for (int ks = 0; ks < 4; ks++) {
            uint32_t ah[4][4], al[4][4], bh[4][2], bl[4][2];
            #pragma unroll
            for (int i = 0; i < 4; i++) {
                int row = wm + i * 16 + (lane & 15);
                int ch = 2 * ks + (lane >> 4);
                uint32_t off = (uint32_t)(row * 128) +
                               (uint32_t)(((ch ^ (row & 7)) << 4));
                ldsm_x4(ah[i], st + off);
                ldsm_x4(al[i], st + 16384u + off);
            }
            #pragma unroll
            for (int jj = 0; jj < 2; jj++) {
                int row = wn + jj * 16 + ((lane >> 4) << 3) + (lane & 7);
                int ch = 2 * ks + ((lane >> 3) & 1);
                uint32_t off = (uint32_t)(row * 128) +
                               (uint32_t)(((ch ^ (row & 7)) << 4));
                uint32_t t[4];
                ldsm_x4(t, st + 32768u + off);
                bh[2 * jj][0] = t[0]; bh[2 * jj][1] = t[1];
                bh[2 * jj + 1][0] = t[2]; bh[2 * jj + 1][1] = t[3];
                ldsm_x4(t, st + 49152u + off);
                bl[2 * jj][0] = t[0]; bl[2 * jj][1] = t[1];
                bl[2 * jj + 1][0] = t[2]; bl[2 * jj + 1][1] = t[3];
            }
            #pragma unroll
            for (int i = 0; i < 4; i++)
                #pragma unroll
                for (int j = 0; j < 4; j++) {
                    mma_bf16(acc[i][j], ah[i], bh[j]);
                    mma_bf16(acc[i][j], al[i], bh[j]);
                    mma_bf16(acc[i][j], ah[i], bl[j]);
                }
        }
    };

    load_stage(0, 0);
    load_stage(1, 1);

    #pragma unroll 1
    for (int c = 0; c < NCH; c++) {
        if (c == NCH - 1) cp_wait<0>(); else cp_wait<1>();
        __syncthreads();
        if (c + 2 < NCH) load_stage(c + 2, (c + 2) % 3);
        compute_stage(c % 3);
    }
    __syncthreads();

    // Epilogue: regs -> padded smem -> coalesced gmem + bias
    float* stg = reinterpret_cast<float*>(smem);     // [128][132]
    #pragma unroll
    for (int i = 0; i < 4; i++) {
        int row = wm + i * 16 + (lane >> 2);
        #pragma unroll
        for (int j = 0; j < 4; j++) {
            int col = wn + j * 8 + (lane & 3) * 2;
            stg[row * 132 + col]           = acc[i][j][0];
            stg[row * 132 + col + 1]       = acc[i][j][1];
            stg[(row + 8) * 132 + col]     = acc[i][j][2];
            stg[(row + 8) * 132 + col + 1] = acc[i][j][3];
        }
    }
    __syncthreads();

    #pragma unroll
    for (int it = 0; it < 16; it++) {
        int idx = it * 256 + tid;         // 4096 float4 slots
        int r = idx >> 5;
        int c4 = (idx & 31) << 2;
        float4 v = *reinterpret_cast<const float4*>(&stg[r * 132 + c4]);
        const float4 b = *reinterpret_cast<const float4*>(&bias[n0 + c4]);
        v.x += b.x; v.y += b.y; v.z += b.z; v.w += b.w;
        *reinterpret_cast<float4*>(&out[(size_t)(m0 + r) * 1024 + n0 + c4]) = v;
    }
}

// ---------------------------------------------------------------------------
// LIF scan over T (soft reset) + time-mean pooling; 16-deep prefetch.
// ---------------------------------------------------------------------------
__global__ __launch_bounds__(128)
void lif_kernel(const float* __restrict__ h2, float* __restrict__ pooled)
{
    int idx = blockIdx.x * 128 + threadIdx.x;   // 0..32767
    int b = idx >> 10;
    int g = idx & 1023;
    const float* p = h2 + ((size_t)b << 20) + g;

    float v = 0.0f, acc = 0.0f;
    for (int t0 = 0; t0 < 1024; t0 += 16) {
        float xv[16];
        #pragma unroll
        for (int i = 0; i < 16; i++)
            xv[i] = __ldg(p + (size_t)(t0 + i) * 1024);
        #pragma unroll
        for (int i = 0; i < 16; i++) {
            v = __fadd_rn(v, __fmul_rn(__fsub_rn(xv[i], v), 0.5f));
            if (v >= 1.0f) { acc += 1.0f; v = __fsub_rn(v, 1.0f); }
        }
    }
    pooled[idx] = acc * (1.0f / 1024.0f);
}

// ---------------------------------------------------------------------------
// out[b,o] = sum_g pooled[b,g] * W_out[o,g] + b_out[o]
// ---------------------------------------------------------------------------
__global__ __launch_bounds__(256)
void head_kernel(const float* __restrict__ pooled,
                 const float* __restrict__ W_out,
                 const float* __restrict__ b_out,
                 float* __restrict__ out)
{
    int b = blockIdx.x / 10;
    int o = blockIdx.x % 10;
    float s = 0.0f;
    for (int g = threadIdx.x; g < 1024; g += 256)
        s = fmaf(pooled[b * 1024 + g], W_out[o * 1024 + g], s);
    s = block_reduce_sum(s);
    if (threadIdx.x == 0) out[blockIdx.x] = s + b_out[o];
}

// ---------------------------------------------------------------------------
extern "C" void kernel_launch(void* const* d_in, const int* in_sizes, int n_in,
                              void* d_out, int out_size)
{
    (void)in_sizes; (void)n_in; (void)out_size;
    const float* x      = (const float*)d_in[0];
    const float* W_proj = (const float*)d_in[1];
    const float* b_proj = (const float*)d_in[2];
    const float* W_hid  = (const float*)d_in[3];
    const float* b_hid  = (const float*)d_in[4];
    const float* W_out  = (const float*)d_in[5];
    const float* b_out  = (const float*)d_in[6];
    float* out = (float*)d_out;

    float *wcomb, *bcomb, *h2, *pooled;
    __nv_bfloat16 *xhi, *xlo, *whi, *wlo;
    cudaGetSymbolAddress((void**)&wcomb,  g_wcomb);
    cudaGetSymbolAddress((void**)&bcomb,  g_bcomb);
    cudaGetSymbolAddress((void**)&h2,     g_h2);
    cudaGetSymbolAddress((void**)&pooled, g_pooled);
    cudaGetSymbolAddress((void**)&xhi,    g_xhi);
    cudaGetSymbolAddress((void**)&xlo,    g_xlo);
    cudaGetSymbolAddress((void**)&whi,    g_whi);
    cudaGetSymbolAddress((void**)&wlo,    g_wlo);

    // 1) b_comb = W_hid @ b_proj + b_hid
    bias_comb_kernel<<<1024, 256>>>(W_hid, b_proj, b_hid, bcomb);
    // 2) W_comb = W_hid @ W_proj (fp32)
    sgemm_nn_kernel<<<dim3(8, 8), 256>>>(W_hid, W_proj, wcomb, 1024, 1024, 1024);
    // 3) bf16 splits
    split_kernel<<<1024, 256>>>(wcomb, whi, wlo, 1024 * 1024 / 4);
    split_kernel<<<32768, 256>>>(x, xhi, xlo, 32 * 1024 * 1024 / 4);
    // 4) main tensor-core GEMM -> h2  (grid: n x m)
    cudaFuncSetAttribute(snn_gemm, cudaFuncAttributeMaxDynamicSharedMemorySize,
                         3 * (int)STAGE);
    snn_gemm<<<dim3(8, 256), 256, 3 * STAGE>>>(xhi, xlo, whi, wlo, bcomb, h2);
    // 5) LIF + pool
    lif_kernel<<<256, 128>>>(h2, pooled);
    // 6) head
    head_kernel<<<320, 256>>>(pooled, W_out, b_out, out);
}

// round 5
// speedup vs baseline: 2.5231x; 1.0417x over previous
#include <cuda_runtime.h>
#include <cuda_fp16.h>
#include <cstdint>
#include <cstddef>

#define DINL __device__ __forceinline__

// ---------------------------------------------------------------------------
// Scratch (device globals; no allocation allowed)
// ---------------------------------------------------------------------------
__device__ float g_wcomb[1024u * 1024u];
__device__ float g_wprojT[1024u * 1024u];
__device__ float g_bcomb[1024];
__device__ float g_h2[32u * 1024u * 1024u];     // [B*T, H] fp32 (134 MB)
__device__ float g_pooled[32 * 1024];
__device__ __align__(16) __half g_xhi[32u * 1024u * 1024u];
__device__ __align__(16) __half g_xlo[32u * 1024u * 1024u];
__device__ __align__(16) __half g_whi[1024u * 1024u];
__device__ __align__(16) __half g_wlo[1024u * 1024u];
__device__ __align__(16) __half g_ahi[1024u * 1024u];   // W_hid split
__device__ __align__(16) __half g_alo[1024u * 1024u];
__device__ __align__(16) __half g_bthi[1024u * 1024u];  // W_projT split
__device__ __align__(16) __half g_btlo[1024u * 1024u];

// Residual scale: lo' = (x - hi) * 2^12, combined as acc1 + acc2 * 2^-12.
static constexpr float LO_SCALE = 4096.0f;
static constexpr float LO_INV   = 1.0f / 4096.0f;

// ---------------------------------------------------------------------------
// PTX helpers (baseline compute_103-safe: cp.async, ldmatrix, mma.sync)
// ---------------------------------------------------------------------------
DINL uint32_t smem_u32(const void* p) {
    uint32_t r;
    asm("{ .reg .u64 t; cvta.to.shared.u64 t, %1; cvt.u32.u64 %0, t; }"
        : "=r"(r) : "l"(p));
    return r;
}
DINL void cp16(uint32_t dst, const void* src) {
    asm volatile("cp.async.cg.shared.global [%0], [%1], 16;"
                 :: "r"(dst), "l"(src) : "memory");
}
DINL void cp_commit() { asm volatile("cp.async.commit_group;" ::: "memory"); }
template <int N> DINL void cp_wait() {
    asm volatile("cp.async.wait_group %0;" :: "n"(N) : "memory");
}
DINL void ldsm_x4(uint32_t* r, uint32_t addr) {
    asm volatile("ldmatrix.sync.aligned.m8n8.x4.shared.b16 {%0,%1,%2,%3}, [%4];"
                 : "=r"(r[0]), "=r"(r[1]), "=r"(r[2]), "=r"(r[3]) : "r"(addr));
}
DINL void mma_f16(float* d, const uint32_t* a, const uint32_t* b) {
    asm volatile(
        "mma.sync.aligned.m16n8k16.row.col.f32.f16.f16.f32 "
        "{%0,%1,%2,%3}, {%4,%5,%6,%7}, {%8,%9}, {%0,%1,%2,%3};"
        : "+f"(d[0]), "+f"(d[1]), "+f"(d[2]), "+f"(d[3])
        : "r"(a[0]), "r"(a[1]), "r"(a[2]), "r"(a[3]), "r"(b[0]), "r"(b[1]));
}

// ---------------------------------------------------------------------------
// Block reduction helper (256 threads)
// ---------------------------------------------------------------------------
DINL float block_reduce_sum(float v) {
    __shared__ float sh[8];
    int lane = threadIdx.x & 31;
    int w = threadIdx.x >> 5;
    #pragma unroll
    for (int o = 16; o > 0; o >>= 1) v += __shfl_down_sync(0xFFFFFFFFu, v, o);
    if (lane == 0) sh[w] = v;
    __syncthreads();
    if (w == 0) {
        v = (lane < 8) ? sh[lane] : 0.0f;
        #pragma unroll
        for (int o = 4; o > 0; o >>= 1) v += __shfl_down_sync(0xFFFFFFFFu, v, o);
    }
    return v;
}

// ---------------------------------------------------------------------------
// b_comb[g] = sum_h W_hid[g,h] * b_proj[h] + b_hid[g]
// ---------------------------------------------------------------------------
__global__ __launch_bounds__(256)
void bias_comb_kernel(const float* __restrict__ W_hid,
                      const float* __restrict__ b_proj,
                      const float* __restrict__ b_hid,
                      float* __restrict__ bcomb)
{
    int g = blockIdx.x;
    float s = 0.0f;
    for (int h = threadIdx.x; h < 1024; h += 256)
        s = fmaf(W_hid[g * 1024 + h], b_proj[h], s);
    s = block_reduce_sum(s);
    if (threadIdx.x == 0) bcomb[g] = s + b_hid[g];
}

// ---------------------------------------------------------------------------
// 1024x1024 fp32 transpose (W_proj -> W_projT)
// ---------------------------------------------------------------------------
__global__ __launch_bounds__(256)
void transpose_kernel(const float* __restrict__ in, float* __restrict__ out)
{
    __shared__ float tile[32][33];
    int x = blockIdx.x * 32 + threadIdx.x;
    int y = blockIdx.y * 32 + threadIdx.y;
    #pragma unroll
    for (int j = 0; j < 32; j += 8)
        tile[threadIdx.y + j][threadIdx.x] = in[(size_t)(y + j) * 1024 + x];
    __syncthreads();
    x = blockIdx.y * 32 + threadIdx.x;
    y = blockIdx.x * 32 + threadIdx.y;
    #pragma unroll
    for (int j = 0; j < 32; j += 8)
        out[(size_t)(y + j) * 1024 + x] = tile[threadIdx.x][threadIdx.y + j];
}

// ---------------------------------------------------------------------------
// fp32 -> (fp16 hi, fp16 lo*4096) split, vectorized.
// Scaling keeps residuals in fp16 normal range (avoids subnormal flush).
// ---------------------------------------------------------------------------
__global__ __launch_bounds__(256)
void split_kernel(const float* __restrict__ src,
                  __half* __restrict__ hi, __half* __restrict__ lo, int n4)
{
    int i = blockIdx.x * 256 + threadIdx.x;
    if (i >= n4) return;
    float4 v = reinterpret_cast<const float4*>(src)[i];
    float f[4] = {v.x, v.y, v.z, v.w};
    uint32_t hw[2], lw[2];
    #pragma unroll
    for (int j = 0; j < 2; j++) {
        __half h0 = __float2half_rn(f[2 * j + 0]);
        __half h1 = __float2half_rn(f[2 * j + 1]);
        __half l0 = __float2half_rn((f[2 * j + 0] - __half2float(h0)) * LO_SCALE);
        __half l1 = __float2half_rn((f[2 * j + 1] - __half2float(h1)) * LO_SCALE);
        unsigned short uh0 = *reinterpret_cast<unsigned short*>(&h0);
        unsigned short uh1 = *reinterpret_cast<unsigned short*>(&h1);
        unsigned short ul0 = *reinterpret_cast<unsigned short*>(&l0);
        unsigned short ul1 = *reinterpret_cast<unsigned short*>(&l1);
        hw[j] = (uint32_t)uh0 | ((uint32_t)uh1 << 16);
        lw[j] = (uint32_t)ul0 | ((uint32_t)ul1 << 16);
    }
    reinterpret_cast<uint2*>(hi)[i] = make_uint2(hw[0], hw[1]);
    reinterpret_cast<uint2*>(lo)[i] = make_uint2(lw[0], lw[1]);
}

// ---------------------------------------------------------------------------
// Split-precision GEMM: C[m,n] = sum_k A[m,k]*B[n,k] (+bias[n] if non-null)
// hi*hi -> acc1 ; (lo'*hi + hi*lo') -> acc2 ; C = acc1 + acc2/4096.
// Tile 128x128, BK=64, 8 warps (2x4), 3-stage cp.async. K fixed at 1024.
// Grid: (N/128, M/128).
// ---------------------------------------------------------------------------
static constexpr uint32_t STAGE = 65536u;   // Ahi16K Alo16K Bhi16K Blo16K
static constexpr int NCH = 16;              // K=1024 / 64

__global__ __launch_bounds__(256, 1)
void hmma_gemm(const __half* __restrict__ Ahi, const __half* __restrict__ Alo,
               const __half* __restrict__ Bhi, const __half* __restrict__ Blo,
               const float* __restrict__ bias, float* __restrict__ out)
{
    extern __shared__ __align__(1024) char smem[];
    const uint32_t sbase = smem_u32(smem);
    const int tid = threadIdx.x;
    const int wid = tid >> 5;
    const int lane = tid & 31;
    const int wm = (wid >> 2) * 64;
    const int wn = (wid & 3) * 32;
    const int m0 = blockIdx.y << 7;
    const int n0 = blockIdx.x << 7;

    float acc1[4][4][4], acc2[4][4][4];
    #pragma unroll
    for (int i = 0; i < 4; i++)
        #pragma unroll
        for (int j = 0; j < 4; j++)
            #pragma unroll
            for (int r = 0; r < 4; r++) { acc1[i][j][r] = 0.0f; acc2[i][j][r] = 0.0f; }

    auto load_stage = [&](int c, int s) {
        const uint32_t st = sbase + (uint32_t)s * STAGE;
        const int k0 = c << 6;
        #pragma unroll
        for (int it = 0; it < 4; it++) {
            int idx = it * 256 + tid;            // 0..1023
            int row = idx >> 3;
            int ch = idx & 7;
            uint32_t off = (uint32_t)(row * 128) +
                           (uint32_t)(((ch ^ (row & 7)) << 4));
            size_t ga = (size_t)(m0 + row) * 1024 + k0 + ch * 8;
            size_t gb = (size_t)(n0 + row) * 1024 + k0 + ch * 8;
            cp16(st + off,          Ahi + ga);
            cp16(st + 16384u + off, Alo + ga);
            cp16(st + 32768u + off, Bhi + gb);
            cp16(st + 49152u + off, Blo + gb);
        }
        cp_commit();
    };

    load_stage(0, 0);
    load_stage(1, 1);

    #pragma unroll 1
    for (int c = 0; c < NCH; c++) {
        if (c == NCH - 1) cp_wait<0>(); else cp_wait<1>();
        __syncthreads();
        if (c + 2 < NCH) load_stage(c + 2, (c + 2) % 3);

        const uint32_t st = sbase + (uint32_t)(c % 3) * STAGE;
        #pragma unroll
        for (int ks = 0; ks < 4; ks++) {
            uint32_t ah[4][4], al[4][4], bh[4][2], bl[4][2];
            #pragma unroll
            for (int i = 0; i < 4; i++) {
                int row = wm + i * 16 + (lane & 15);
                int ch = 2 * ks + (lane >> 4);
                uint32_t off = (uint32_t)(row * 128) +
                               (uint32_t)(((ch ^ (row & 7)) << 4));
                ldsm_x4(ah[i], st + off);
                ldsm_x4(al[i], st + 16384u + off);
            }
            #pragma unroll
            for (int jj = 0; jj < 2; jj++) {
                int row = wn + jj * 16 + ((lane >> 4) << 3) + (lane & 7);
                int ch = 2 * ks + ((lane >> 3) & 1);
                uint32_t off = (uint32_t)(row * 128) +
                               (uint32_t)(((ch ^ (row & 7)) << 4));
                uint32_t t[4];
                ldsm_x4(t, st + 32768u + off);
                bh[2 * jj][0] = t[0]; bh[2 * jj][1] = t[1];
                bh[2 * jj + 1][0] = t[2]; bh[2 * jj + 1][1] = t[3];
                ldsm_x4(t, st + 49152u + off);
                bl[2 * jj][0] = t[0]; bl[2 * jj][1] = t[1];
                bl[2 * jj + 1][0] = t[2]; bl[2 * jj + 1][1] = t[3];
            }
            #pragma unroll
            for (int i = 0; i < 4; i++)
                #pragma unroll
                for (int j = 0; j < 4; j++) {
                    mma_f16(acc1[i][j], ah[i], bh[j]);
                    mma_f16(acc2[i][j], al[i], bh[j]);
                    mma_f16(acc2[i][j], ah[i], bl[j]);
                }
        }
    }
    __syncthreads();

    // Epilogue: combine acc1 + acc2/4096 -> padded smem -> coalesced gmem
    float* stg = reinterpret_cast<float*>(smem);     // [128][132]
    #pragma unroll
    for (int i = 0; i < 4; i++) {
        int row = wm + i * 16 + (lane >> 2);
        #pragma unroll
        for (int j = 0; j < 4; j++) {
            int col = wn + j * 8 + (lane & 3) * 2;
            stg[row * 132 + col]           = fmaf(acc2[i][j][0], LO_INV, acc1[i][j][0]);
            stg[row * 132 + col + 1]       = fmaf(acc2[i][j][1], LO_INV, acc1[i][j][1]);
            stg[(row + 8) * 132 + col]     = fmaf(acc2[i][j][2], LO_INV, acc1[i][j][2]);
            stg[(row + 8) * 132 + col + 1] = fmaf(acc2[i][j][3], LO_INV, acc1[i][j][3]);
        }
    }
    __syncthreads();

    #pragma unroll
    for (int it = 0; it < 16; it++) {
        int idx = it * 256 + tid;
        int r = idx >> 5;
        int c4 = (idx & 31) << 2;
        float4 v = *reinterpret_cast<const float4*>(&stg[r * 132 + c4]);
        if (bias != nullptr) {
            const float4 b = *reinterpret_cast<const float4*>(&bias[n0 + c4]);
            v.x += b.x; v.y += b.y; v.z += b.z; v.w += b.w;
        }
        *reinterpret_cast<float4*>(&out[(size_t)(m0 + r) * 1024 + n0 + c4]) = v;
    }
}

// ---------------------------------------------------------------------------
// LIF scan over T (soft reset) + time-mean pooling. float4 per thread,
// 16-deep prefetch (2 MB in flight chip-wide).
// ---------------------------------------------------------------------------
__global__ __launch_bounds__(128)
void lif_kernel(const float* __restrict__ h2, float* __restrict__ pooled)
{
    int idx = blockIdx.x * 128 + threadIdx.x;   // 0..8191
    int b = idx >> 8;
    int g4 = idx & 255;
    const float4* p = reinterpret_cast<const float4*>(h2 + ((size_t)b << 20)) + g4;

    float v[4] = {0, 0, 0, 0}, acc[4] = {0, 0, 0, 0};
    for (int t0 = 0; t0 < 1024; t0 += 16) {
        float4 xv[16];
        #pragma unroll
        for (int i = 0; i < 16; i++)
            xv[i] = __ldg(p + (size_t)(t0 + i) * 256);
        #pragma unroll
        for (int i = 0; i < 16; i++) {
            float xs[4] = {xv[i].x, xv[i].y, xv[i].z, xv[i].w};
            #pragma unroll
            for (int c = 0; c < 4; c++) {
                v[c] = __fadd_rn(v[c], __fmul_rn(__fsub_rn(xs[c], v[c]), 0.5f));
                if (v[c] >= 1.0f) { acc[c] += 1.0f; v[c] = __fsub_rn(v[c], 1.0f); }
            }
        }
    }
    float4 r;
    r.x = acc[0] * (1.0f / 1024.0f); r.y = acc[1] * (1.0f / 1024.0f);
    r.z = acc[2] * (1.0f / 1024.0f); r.w = acc[3] * (1.0f / 1024.0f);
    reinterpret_cast<float4*>(pooled)[idx] = r;
}

// ---------------------------------------------------------------------------
// out[b,o] = sum_g pooled[b,g] * W_out[o,g] + b_out[o]
// ---------------------------------------------------------------------------
__global__ __launch_bounds__(256)
void head_kernel(const float* __restrict__ pooled,
                 const float* __restrict__ W_out,
                 const float* __restrict__ b_out,
                 float* __restrict__ out)
{
    int b = blockIdx.x / 10;
    int o = blockIdx.x % 10;
    float s = 0.0f;
    for (int g = threadIdx.x; g < 1024; g += 256)
        s = fmaf(pooled[b * 1024 + g], W_out[o * 1024 + g], s);
    s = block_reduce_sum(s);
    if (threadIdx.x == 0) out[blockIdx.x] = s + b_out[o];
}

// ---------------------------------------------------------------------------
extern "C" void kernel_launch(void* const* d_in, const int* in_sizes, int n_in,
                              void* d_out, int out_size)
{
    (void)in_sizes; (void)n_in; (void)out_size;
    const float* x      = (const float*)d_in[0];
    const float* W_proj = (const float*)d_in[1];
    const float* b_proj = (const float*)d_in[2];
    const float* W_hid  = (const float*)d_in[3];
    const float* b_hid  = (const float*)d_in[4];
    const float* W_out  = (const float*)d_in[5];
    const float* b_out  = (const float*)d_in[6];
    float* out = (float*)d_out;

    float *wcomb, *wprojT, *bcomb, *h2, *pooled;
    __half *xhi, *xlo, *whi, *wlo, *ahi, *alo, *bthi, *btlo;
    cudaGetSymbolAddress((void**)&wcomb,  g_wcomb);
    cudaGetSymbolAddress((void**)&wprojT, g_wprojT);
    cudaGetSymbolAddress((void**)&bcomb,  g_bcomb);
    cudaGetSymbolAddress((void**)&h2,     g_h2);
    cudaGetSymbolAddress((void**)&pooled, g_pooled);
    cudaGetSymbolAddress((void**)&xhi,    g_xhi);
    cudaGetSymbolAddress((void**)&xlo,    g_xlo);
    cudaGetSymbolAddress((void**)&whi,    g_whi);
    cudaGetSymbolAddress((void**)&wlo,    g_wlo);
    cudaGetSymbolAddress((void**)&ahi,    g_ahi);
    cudaGetSymbolAddress((void**)&alo,    g_alo);
    cudaGetSymbolAddress((void**)&bthi,   g_bthi);
    cudaGetSymbolAddress((void**)&btlo,   g_btlo);

    cudaFuncSetAttribute(hmma_gemm, cudaFuncAttributeMaxDynamicSharedMemorySize,
                         3 * (int)STAGE);

    // 1) b_comb = W_hid @ b_proj + b_hid
    bias_comb_kernel<<<1024, 256>>>(W_hid, b_proj, b_hid, bcomb);
    // 2) W_projT = W_proj^T ; splits of W_hid / W_projT
    transpose_kernel<<<dim3(32, 32), dim3(32, 8)>>>(W_proj, wprojT);
    split_kernel<<<1024, 256>>>(W_hid,  ahi,  alo,  1024 * 1024 / 4);
    split_kernel<<<1024, 256>>>(wprojT, bthi, btlo, 1024 * 1024 / 4);
    // 3) W_comb[g,d] = sum_h W_hid[g,h] * W_projT[d,h]   (tensor cores)
    hmma_gemm<<<dim3(8, 8), 256, 3 * STAGE>>>(ahi, alo, bthi, btlo, nullptr, wcomb);
    // 4) splits for the main GEMM
    split_kernel<<<1024, 256>>>(wcomb, whi, wlo, 1024 * 1024 / 4);
    split_kernel<<<32768, 256>>>(x, xhi, xlo, 32 * 1024 * 1024 / 4);
    // 5) h2 = x @ W_comb^T + b_comb
    hmma_gemm<<<dim3(8, 256), 256, 3 * STAGE>>>(xhi, xlo, whi, wlo, bcomb, h2);
    // 6) LIF + pool
    lif_kernel<<<64, 128>>>(h2, pooled);
    // 7) head
    head_kernel<<<320, 256>>>(pooled, W_out, b_out, out);
}